// round 2
// baseline (speedup 1.0000x reference)
#include <cuda_runtime.h>
#include <cuda_bf16.h>
#include <mma.h>

using namespace nvcuda;

// Problem constants
#define BATCH   8192
#define S_IN    4096
#define S_OUT   4096
#define HID     128
#define ARN     7

// GEMM tiling
#define BM 64
#define BK 32
#define GEMM_THREADS 256

// Scratch for hidden activations (allowed: __device__ globals, no runtime alloc)
__device__ float g_h1[BATCH * HID];
__device__ float g_h2[BATCH * HID];

// ---------------------------------------------------------------------------
// AR filter: one thread per batch row.
//   y[t] = n[t] + sum_i c[i]*y[t-1-i]  for t >= 7;  y[t] = 0 for t < 7.
// Critical-path optimization: only c0*y[t-1] is on the 1-step recurrence.
// Taps c2..c6 are summed first (their inputs are >=3 steps old), then the
// chain ends with fma(c1,y2) -> fma(c0,y1): 2 dependent FMAs per step.
// Unroll-8 with 2x float4 loads/stores for full-sector coalescing.
// ---------------------------------------------------------------------------
__global__ __launch_bounds__(256) void ar_kernel(
    const float* __restrict__ noise,
    const float* __restrict__ coef,
    float* __restrict__ out)
{
    int b = blockIdx.x * blockDim.x + threadIdx.x;
    if (b >= BATCH) return;

    const float* nr  = noise + (size_t)b * S_OUT;
    float*       orw = out   + (size_t)b * S_OUT;

    const float c0 = coef[0], c1 = coef[1], c2 = coef[2], c3 = coef[3];
    const float c4 = coef[4], c5 = coef[5], c6 = coef[6];

    // history: y1 = y[t-1], ..., y7 = y[t-7]
    float y1 = 0.f, y2 = 0.f, y3 = 0.f, y4 = 0.f, y5 = 0.f, y6 = 0.f, y7 = 0.f;

    float4 z = make_float4(0.f, 0.f, 0.f, 0.f);
    *reinterpret_cast<float4*>(orw + 0) = z;          // t=0..3
    orw[4] = 0.f; orw[5] = 0.f; orw[6] = 0.f;
    {
        float y = nr[7];                               // carry all-zero at t=7
        orw[7] = y;
        y1 = y;
    }

    // acc part (old history, off critical path) then 2-FMA chain.
#define AR_STEP(nv, ov)                                                   \
    {                                                                     \
        float acc = nv;                                                   \
        acc = fmaf(c6, y7, acc);                                          \
        acc = fmaf(c5, y6, acc);                                          \
        acc = fmaf(c4, y5, acc);                                          \
        acc = fmaf(c3, y4, acc);                                          \
        acc = fmaf(c2, y3, acc);                                          \
        acc = fmaf(c1, y2, acc);   /* needs y[t-2]: 2 steps old */        \
        float y = fmaf(c0, y1, acc); /* the only 1-step dependence */     \
        ov = y;                                                           \
        y7 = y6; y6 = y5; y5 = y4; y4 = y3; y3 = y2; y2 = y1; y1 = y;     \
    }

    for (int t = 8; t < S_OUT; t += 8) {
        float4 n0 = *reinterpret_cast<const float4*>(nr + t);
        float4 n1 = *reinterpret_cast<const float4*>(nr + t + 4);
        float4 o0, o1;
        AR_STEP(n0.x, o0.x); AR_STEP(n0.y, o0.y);
        AR_STEP(n0.z, o0.z); AR_STEP(n0.w, o0.w);
        AR_STEP(n1.x, o1.x); AR_STEP(n1.y, o1.y);
        AR_STEP(n1.z, o1.z); AR_STEP(n1.w, o1.w);
        *reinterpret_cast<float4*>(orw + t)     = o0;
        *reinterpret_cast<float4*>(orw + t + 4) = o1;
    }
#undef AR_STEP
}

// ---------------------------------------------------------------------------
// TF32 WMMA GEMM: C[M,N] = epilogue(A[M,K] @ W[N,K]^T + bias)
//   EPI == 0 : C = relu(acc + bias)
//   EPI == 1 : C += tanh(acc + bias)      (C pre-filled by ar_kernel)
// BM=64, BN_=128, BK=32; 8 warps in 2(m) x 4(n); warp tile 32x32
// -> 2x2 m16n16k8 TF32 fragments per warp. Smem union: (As+Bs) | Cs.
// Dims must divide tiles (8192%64, 128%128, 4096%128, K%32 all == 0).
// ---------------------------------------------------------------------------
__device__ __forceinline__ float to_tf32(float x) {
    float r;
    asm("cvt.rna.tf32.f32 %0, %1;" : "=f"(r) : "f"(x));
    return r;
}

template <int BN_, int EPI>
__global__ __launch_bounds__(GEMM_THREADS) void gemm_kernel(
    const float* __restrict__ A,
    const float* __restrict__ W,
    const float* __restrict__ bias,
    float* __restrict__ C,
    int M, int N, int K)
{
    constexpr int WARPS_N = BN_ / 32;             // 4 for BN_=128
    constexpr int WARPS_M = 8 / WARPS_N;          // 2
    constexpr int WTM     = BM / WARPS_M;         // 32
    constexpr int MI      = WTM / 16;             // 2
    constexpr int NI      = 2;                    // 32 / 16

    constexpr int A_ELEMS = BM * (BK + 4);
    constexpr int B_ELEMS = BK * (BN_ + 4);
    constexpr int C_ELEMS = BM * BN_;
    constexpr int SMEM_ELEMS =
        (A_ELEMS + B_ELEMS > C_ELEMS) ? (A_ELEMS + B_ELEMS) : C_ELEMS;

    __shared__ __align__(16) float smem[SMEM_ELEMS];
    float (*As)[BK + 4]  = reinterpret_cast<float (*)[BK + 4]>(smem);
    float (*Bs)[BN_ + 4] = reinterpret_cast<float (*)[BN_ + 4]>(smem + A_ELEMS);
    float (*Cs)[BN_]     = reinterpret_cast<float (*)[BN_]>(smem);

    const int tid     = threadIdx.x;
    const int warp_id = tid >> 5;
    const int wm      = warp_id / WARPS_N;        // 0..WARPS_M-1
    const int wn      = warp_id % WARPS_N;        // 0..WARPS_N-1

    const int m0 = blockIdx.x * BM;
    const int n0 = blockIdx.y * BN_;

    wmma::fragment<wmma::accumulator, 16, 16, 8, float> acc[MI][NI];
    #pragma unroll
    for (int i = 0; i < MI; i++)
        #pragma unroll
        for (int j = 0; j < NI; j++)
            wmma::fill_fragment(acc[i][j], 0.0f);

    for (int k0 = 0; k0 < K; k0 += BK) {
        __syncthreads();
        // --- A tile: BM x BK ---
        #pragma unroll
        for (int i = tid; i < (BM * BK) / 4; i += GEMM_THREADS) {
            int row = (i * 4) / BK;
            int col = (i * 4) % BK;
            float4 v = *reinterpret_cast<const float4*>(
                A + (size_t)(m0 + row) * K + k0 + col);
            As[row][col + 0] = to_tf32(v.x);
            As[row][col + 1] = to_tf32(v.y);
            As[row][col + 2] = to_tf32(v.z);
            As[row][col + 3] = to_tf32(v.w);
        }
        // --- B tile transposed: Bs[k][n] = W[n0+n][k0+k] ---
        #pragma unroll
        for (int i = tid; i < (BN_ * BK) / 4; i += GEMM_THREADS) {
            int n  = i / (BK / 4);
            int kq = (i % (BK / 4)) * 4;
            float4 v = *reinterpret_cast<const float4*>(
                W + (size_t)(n0 + n) * K + k0 + kq);
            Bs[kq + 0][n] = to_tf32(v.x);
            Bs[kq + 1][n] = to_tf32(v.y);
            Bs[kq + 2][n] = to_tf32(v.z);
            Bs[kq + 3][n] = to_tf32(v.w);
        }
        __syncthreads();

        #pragma unroll
        for (int kk = 0; kk < BK; kk += 8) {
            wmma::fragment<wmma::matrix_a, 16, 16, 8, wmma::precision::tf32,
                           wmma::row_major> a[MI];
            #pragma unroll
            for (int i = 0; i < MI; i++)
                wmma::load_matrix_sync(a[i], &As[wm * WTM + i * 16][kk], BK + 4);
            #pragma unroll
            for (int j = 0; j < NI; j++) {
                wmma::fragment<wmma::matrix_b, 16, 16, 8, wmma::precision::tf32,
                               wmma::row_major> bfrag;
                wmma::load_matrix_sync(bfrag, &Bs[kk][wn * 32 + j * 16], BN_ + 4);
                #pragma unroll
                for (int i = 0; i < MI; i++)
                    wmma::mma_sync(acc[i][j], a[i], bfrag, acc[i][j]);
            }
        }
    }

    __syncthreads();   // done with As/Bs; Cs aliases them
    #pragma unroll
    for (int i = 0; i < MI; i++)
        #pragma unroll
        for (int j = 0; j < NI; j++)
            wmma::store_matrix_sync(&Cs[wm * WTM + i * 16][wn * 32 + j * 16],
                                    acc[i][j], BN_, wmma::mem_row_major);
    __syncthreads();

    // Epilogue: bias + activation (+ accumulate). Coalesced over n.
    #pragma unroll 4
    for (int i = tid; i < BM * BN_; i += GEMM_THREADS) {
        int m = i / BN_;
        int n = i % BN_;
        float v = Cs[m][n] + bias[n0 + n];
        size_t oidx = (size_t)(m0 + m) * N + n0 + n;
        if (EPI == 0) {
            C[oidx] = fmaxf(v, 0.0f);
        } else {
            C[oidx] += tanhf(v);
        }
    }
}

// ---------------------------------------------------------------------------
// Launch: AR -> d_out; GEMM1 relu -> h1; GEMM2 relu -> h2; GEMM3 tanh += d_out.
// One (captured) stream; stream order serializes the d_out read-modify-write.
// ---------------------------------------------------------------------------
extern "C" void kernel_launch(void* const* d_in, const int* in_sizes, int n_in,
                              void* d_out, int out_size)
{
    const float* x       = (const float*)d_in[0];
    const float* noise   = (const float*)d_in[1];
    const float* W1      = (const float*)d_in[2];
    const float* b1      = (const float*)d_in[3];
    const float* W2      = (const float*)d_in[4];
    const float* b2      = (const float*)d_in[5];
    const float* W3      = (const float*)d_in[6];
    const float* b3      = (const float*)d_in[7];
    const float* ar_coef = (const float*)d_in[8];
    float* out = (float*)d_out;

    float* h1 = nullptr;
    float* h2 = nullptr;
    cudaGetSymbolAddress((void**)&h1, g_h1);
    cudaGetSymbolAddress((void**)&h2, g_h2);

    // AR recurrence writes the full output buffer (incl. zero head).
    ar_kernel<<<BATCH / 256, 256>>>(noise, ar_coef, out);

    // h1 = relu(x @ W1^T + b1)        M=8192 N=128 K=4096, x read exactly once
    gemm_kernel<128, 0><<<dim3(BATCH / BM, HID / 128), GEMM_THREADS>>>(
        x, W1, b1, h1, BATCH, HID, S_IN);

    // h2 = relu(h1 @ W2^T + b2)       M=8192 N=128 K=128
    gemm_kernel<128, 0><<<dim3(BATCH / BM, HID / 128), GEMM_THREADS>>>(
        h1, W2, b2, h2, BATCH, HID, HID);

    // out += tanh(h2 @ W3^T + b3)     M=8192 N=4096 K=128
    gemm_kernel<128, 1><<<dim3(BATCH / BM, S_OUT / 128), GEMM_THREADS>>>(
        h2, W3, b3, out, BATCH, S_OUT, HID);
}

// round 14
// speedup vs baseline: 1.6943x; 1.6943x over previous
#include <cuda_runtime.h>
#include <cuda_bf16.h>
#include <cuda_pipeline.h>
#include <mma.h>

using namespace nvcuda;

// Problem constants
#define BATCH   8192
#define S_IN    4096
#define S_OUT   4096
#define HID     128
#define ARN     7
#define KSPLIT  8
#define KLEN    (S_IN / KSPLIT)   // 512

// Scratch (device globals; no runtime allocation)
__device__ float g_h1part[KSPLIT * BATCH * HID];   // 32 MB split-K partials
__device__ float g_h1[BATCH * HID];
__device__ float g_h2[BATCH * HID];

// ---------------------------------------------------------------------------
// AR filter: one thread per batch row; 2-FMA critical path per step.
// y[t] = n[t] + sum_i c[i]*y[t-1-i] (t>=7), 0 before. Writes all of d_out.
// ---------------------------------------------------------------------------
__global__ __launch_bounds__(64) void ar_kernel(
    const float* __restrict__ noise,
    const float* __restrict__ coef,
    float* __restrict__ out)
{
    int b = blockIdx.x * blockDim.x + threadIdx.x;
    if (b >= BATCH) return;

    const float* nr  = noise + (size_t)b * S_OUT;
    float*       orw = out   + (size_t)b * S_OUT;

    const float c0 = coef[0], c1 = coef[1], c2 = coef[2], c3 = coef[3];
    const float c4 = coef[4], c5 = coef[5], c6 = coef[6];

    float y1 = 0.f, y2 = 0.f, y3 = 0.f, y4 = 0.f, y5 = 0.f, y6 = 0.f, y7 = 0.f;

    float4 z = make_float4(0.f, 0.f, 0.f, 0.f);
    *reinterpret_cast<float4*>(orw + 0) = z;
    orw[4] = 0.f; orw[5] = 0.f; orw[6] = 0.f;
    { float y = nr[7]; orw[7] = y; y1 = y; }

#define AR_STEP(nv, ov)                                                   \
    {                                                                     \
        float acc = nv;                                                   \
        acc = fmaf(c6, y7, acc);                                          \
        acc = fmaf(c5, y6, acc);                                          \
        acc = fmaf(c4, y5, acc);                                          \
        acc = fmaf(c3, y4, acc);                                          \
        acc = fmaf(c2, y3, acc);                                          \
        acc = fmaf(c1, y2, acc);   /* 2 steps old */                      \
        float y = fmaf(c0, y1, acc); /* only 1-step dependence */         \
        ov = y;                                                           \
        y7 = y6; y6 = y5; y5 = y4; y4 = y3; y3 = y2; y2 = y1; y1 = y;     \
    }

    for (int t = 8; t < S_OUT; t += 8) {
        float4 n0 = *reinterpret_cast<const float4*>(nr + t);
        float4 n1 = *reinterpret_cast<const float4*>(nr + t + 4);
        float4 o0, o1;
        AR_STEP(n0.x, o0.x); AR_STEP(n0.y, o0.y);
        AR_STEP(n0.z, o0.z); AR_STEP(n0.w, o0.w);
        AR_STEP(n1.x, o1.x); AR_STEP(n1.y, o1.y);
        AR_STEP(n1.z, o1.z); AR_STEP(n1.w, o1.w);
        *reinterpret_cast<float4*>(orw + t)     = o0;
        *reinterpret_cast<float4*>(orw + t + 4) = o1;
    }
#undef AR_STEP
}

// ---------------------------------------------------------------------------
// GEMM1 split-K partial with 2-stage cp.async double buffering.
//   Cpart[split] = x[:, koff:koff+KLEN] @ W1[:, koff:koff+KLEN]^T
// BM=64, BN=128 (full HID), BK=32; grid (BATCH/64, KSPLIT).
// B tile kept natural [n][k]; fragments loaded col_major (no transpose).
// Deterministic: each split owns a partial buffer, reduced afterwards.
// ---------------------------------------------------------------------------
#define G1_AS_ELEMS (64 * 36)
#define G1_BS_ELEMS (128 * 36)
#define G1_SMEM_BYTES ((2 * (G1_AS_ELEMS + G1_BS_ELEMS)) * 4)   // 55296 B

__global__ __launch_bounds__(256) void gemm1_partial(
    const float* __restrict__ A,   // x [8192, 4096]
    const float* __restrict__ W,   // W1 [128, 4096]
    float* __restrict__ Cpart)     // [KSPLIT][8192][128]
{
    extern __shared__ float sm[];
    // layout: As[2][64][36] | Bs[2][128][36]
    float (*As)[64][36]  = reinterpret_cast<float (*)[64][36]>(sm);
    float (*Bs)[128][36] = reinterpret_cast<float (*)[128][36]>(sm + 2 * G1_AS_ELEMS);

    const int tid  = threadIdx.x;
    const int warp = tid >> 5;
    const int wm   = warp >> 2;      // 0..1 (m)
    const int wn   = warp & 3;       // 0..3 (n)

    const size_t m0   = (size_t)blockIdx.x * 64;
    const int    koff = blockIdx.y * KLEN;
    float* C = Cpart + (size_t)blockIdx.y * BATCH * HID;

    constexpr int NIT = KLEN / 32;   // 16

    // async tile issue: A 64x32 (512 16B chunks), B 128x32 (1024 chunks)
    auto issue = [&](int it, int buf) {
        int k0 = koff + it * 32;
        #pragma unroll
        for (int i = tid; i < 512; i += 256) {
            int r = i >> 3, c = (i & 7) * 4;
            __pipeline_memcpy_async(&As[buf][r][c],
                                    &A[(m0 + r) * S_IN + k0 + c], 16);
        }
        #pragma unroll
        for (int i = tid; i < 1024; i += 256) {
            int n = i >> 3, c = (i & 7) * 4;
            __pipeline_memcpy_async(&Bs[buf][n][c],
                                    &W[(size_t)n * S_IN + k0 + c], 16);
        }
        __pipeline_commit();
    };

    wmma::fragment<wmma::accumulator, 16, 16, 8, float> acc[2][2];
    #pragma unroll
    for (int i = 0; i < 2; i++)
        #pragma unroll
        for (int j = 0; j < 2; j++)
            wmma::fill_fragment(acc[i][j], 0.0f);

    issue(0, 0);

    for (int it = 0; it < NIT; it++) {
        int buf = it & 1;
        if (it + 1 < NIT) {
            issue(it + 1, (it + 1) & 1);
            __pipeline_wait_prior(1);
        } else {
            __pipeline_wait_prior(0);
        }
        __syncthreads();

        #pragma unroll
        for (int kk = 0; kk < 32; kk += 8) {
            wmma::fragment<wmma::matrix_a, 16, 16, 8, wmma::precision::tf32,
                           wmma::row_major> a[2];
            #pragma unroll
            for (int i = 0; i < 2; i++)
                wmma::load_matrix_sync(a[i], &As[buf][wm * 32 + i * 16][kk], 36);
            #pragma unroll
            for (int j = 0; j < 2; j++) {
                // col_major: element(k,n) = Bs[n][k]
                wmma::fragment<wmma::matrix_b, 16, 16, 8, wmma::precision::tf32,
                               wmma::col_major> b;
                wmma::load_matrix_sync(b, &Bs[buf][wn * 32 + j * 16][kk], 36);
                #pragma unroll
                for (int i = 0; i < 2; i++)
                    wmma::mma_sync(acc[i][j], a[i], b, acc[i][j]);
            }
        }
        __syncthreads();   // protect buf from being overwritten by it+2's issue
    }

    // Direct fragment store to the partial buffer.
    #pragma unroll
    for (int i = 0; i < 2; i++)
        #pragma unroll
        for (int j = 0; j < 2; j++)
            wmma::store_matrix_sync(
                &C[(m0 + wm * 32 + i * 16) * HID + wn * 32 + j * 16],
                acc[i][j], HID, wmma::mem_row_major);
}

// ---------------------------------------------------------------------------
// Reduce split-K partials + bias + relu -> h1. Vectorized float4.
// ---------------------------------------------------------------------------
__global__ __launch_bounds__(256) void reduce_relu_kernel(
    const float* __restrict__ parts,
    const float* __restrict__ bias,
    float* __restrict__ h1)
{
    int i4 = (blockIdx.x * 256 + threadIdx.x) * 4;   // over BATCH*HID
    float4 a = *reinterpret_cast<const float4*>(parts + i4);
    #pragma unroll
    for (int s = 1; s < KSPLIT; s++) {
        float4 p = *reinterpret_cast<const float4*>(
            parts + (size_t)s * BATCH * HID + i4);
        a.x += p.x; a.y += p.y; a.z += p.z; a.w += p.w;
    }
    int k = i4 & (HID - 1);
    a.x = fmaxf(a.x + bias[k + 0], 0.f);
    a.y = fmaxf(a.y + bias[k + 1], 0.f);
    a.z = fmaxf(a.z + bias[k + 2], 0.f);
    a.w = fmaxf(a.w + bias[k + 3], 0.f);
    *reinterpret_cast<float4*>(h1 + i4) = a;
}

// ---------------------------------------------------------------------------
// Full-K GEMM for K=128 (GEMM2, GEMM3): load whole K into smem ONCE, then an
// uninterrupted 16-step MMA loop (no per-k syncthreads).
//   ACT == 0 : C = relu(acc + bias)
//   ACT == 1 : C += tanh(acc + bias)     (C prefilled by ar_kernel)
// BM=64, BN=64; 8 warps 2(m)x4(n); warp tile 32x16 -> 2 acc fragments.
// B tile natural [n][k]; col_major fragments (no transpose, no conflicts).
// ---------------------------------------------------------------------------
#define FK_AS_ELEMS (64 * 132)
#define FK_BS_ELEMS (64 * 132)
#define FK_SMEM_BYTES ((FK_AS_ELEMS + FK_BS_ELEMS) * 4)   // 67584 B

template <int ACT>
__global__ __launch_bounds__(256) void fullk_gemm(
    const float* __restrict__ A,     // [M, 128]
    const float* __restrict__ W,     // [N, 128]
    const float* __restrict__ bias,  // [N]
    float* __restrict__ C,           // [M, N]
    int N)
{
    extern __shared__ float sm[];
    float (*As)[132] = reinterpret_cast<float (*)[132]>(sm);               // 64x132
    float (*Bs)[132] = reinterpret_cast<float (*)[132]>(sm + FK_AS_ELEMS); // 64x132 [n][k]
    float (*Cs)[68]  = reinterpret_cast<float (*)[68]>(sm);                // reuse

    const int tid  = threadIdx.x;
    const int warp = tid >> 5;
    const int wm   = warp >> 2;      // 0..1
    const int wn   = warp & 3;       // 0..3

    const size_t m0 = (size_t)blockIdx.x * 64;
    const size_t n0 = (size_t)blockIdx.y * 64;

    // Load A tile: 64 rows x 128 K (coalesced, conflict-free row stores)
    #pragma unroll
    for (int i = tid; i < (64 * 128) / 4; i += 256) {
        int r = (i * 4) / 128, c = (i * 4) % 128;
        float4 v = *reinterpret_cast<const float4*>(A + (m0 + r) * HID + c);
        *reinterpret_cast<float4*>(&As[r][c]) = v;
    }
    // Load B tile natural: Bs[n][k] = W[n0+n][k]
    #pragma unroll
    for (int i = tid; i < (64 * 128) / 4; i += 256) {
        int n = (i * 4) / 128, c = (i * 4) % 128;
        float4 v = *reinterpret_cast<const float4*>(W + (n0 + n) * HID + c);
        *reinterpret_cast<float4*>(&Bs[n][c]) = v;
    }
    __syncthreads();

    wmma::fragment<wmma::accumulator, 16, 16, 8, float> acc[2];
    wmma::fill_fragment(acc[0], 0.0f);
    wmma::fill_fragment(acc[1], 0.0f);

    #pragma unroll
    for (int k = 0; k < 128; k += 8) {
        wmma::fragment<wmma::matrix_a, 16, 16, 8, wmma::precision::tf32,
                       wmma::row_major> a0, a1;
        wmma::load_matrix_sync(a0, &As[wm * 32 + 0][k], 132);
        wmma::load_matrix_sync(a1, &As[wm * 32 + 16][k], 132);
        wmma::fragment<wmma::matrix_b, 16, 16, 8, wmma::precision::tf32,
                       wmma::col_major> b;
        wmma::load_matrix_sync(b, &Bs[wn * 16][k], 132);
        wmma::mma_sync(acc[0], a0, b, acc[0]);
        wmma::mma_sync(acc[1], a1, b, acc[1]);
    }

    __syncthreads();   // done with As/Bs; Cs aliases them
    wmma::store_matrix_sync(&Cs[wm * 32 + 0][wn * 16], acc[0], 68,
                            wmma::mem_row_major);
    wmma::store_matrix_sync(&Cs[wm * 32 + 16][wn * 16], acc[1], 68,
                            wmma::mem_row_major);
    __syncthreads();

    // Epilogue: 64x64 tile, coalesced over n.
    #pragma unroll 4
    for (int i = tid; i < 64 * 64; i += 256) {
        int m = i >> 6, n = i & 63;
        float v = Cs[m][n] + bias[n0 + n];
        size_t oidx = (m0 + m) * (size_t)N + n0 + n;
        if (ACT == 0) {
            C[oidx] = fmaxf(v, 0.0f);
        } else {
            C[oidx] += tanhf(v);
        }
    }
}

// ---------------------------------------------------------------------------
// Launch sequence (single captured stream serializes the d_out RMW):
//   ar -> out;  gemm1 partials;  reduce+relu -> h1;
//   fullk<relu>(h1,W2) -> h2;  fullk<tanh-acc>(h2,W3) += out
// ---------------------------------------------------------------------------
extern "C" void kernel_launch(void* const* d_in, const int* in_sizes, int n_in,
                              void* d_out, int out_size)
{
    const float* x       = (const float*)d_in[0];
    const float* noise   = (const float*)d_in[1];
    const float* W1      = (const float*)d_in[2];
    const float* b1      = (const float*)d_in[3];
    const float* W2      = (const float*)d_in[4];
    const float* b2      = (const float*)d_in[5];
    const float* W3      = (const float*)d_in[6];
    const float* b3      = (const float*)d_in[7];
    const float* ar_coef = (const float*)d_in[8];
    float* out = (float*)d_out;

    float *h1part = nullptr, *h1 = nullptr, *h2 = nullptr;
    cudaGetSymbolAddress((void**)&h1part, g_h1part);
    cudaGetSymbolAddress((void**)&h1, g_h1);
    cudaGetSymbolAddress((void**)&h2, g_h2);

    cudaFuncSetAttribute(gemm1_partial,
                         cudaFuncAttributeMaxDynamicSharedMemorySize, G1_SMEM_BYTES);
    cudaFuncSetAttribute(fullk_gemm<0>,
                         cudaFuncAttributeMaxDynamicSharedMemorySize, FK_SMEM_BYTES);
    cudaFuncSetAttribute(fullk_gemm<1>,
                         cudaFuncAttributeMaxDynamicSharedMemorySize, FK_SMEM_BYTES);

    // AR recurrence fills the output buffer (incl. zero head).
    ar_kernel<<<BATCH / 64, 64>>>(noise, ar_coef, out);

    // GEMM1 split-K partials: 128 x 8 = 1024 blocks.
    gemm1_partial<<<dim3(BATCH / 64, KSPLIT), 256, G1_SMEM_BYTES>>>(x, W1, h1part);

    // h1 = relu(sum partials + b1)
    reduce_relu_kernel<<<(BATCH * HID) / (256 * 4), 256>>>(h1part, b1, h1);

    // h2 = relu(h1 @ W2^T + b2): grid 128 x 2
    fullk_gemm<0><<<dim3(BATCH / 64, HID / 64), 256, FK_SMEM_BYTES>>>(
        h1, W2, b2, h2, HID);

    // out += tanh(h2 @ W3^T + b3): grid 128 x 64
    fullk_gemm<1><<<dim3(BATCH / 64, S_OUT / 64), 256, FK_SMEM_BYTES>>>(
        h2, W3, b3, out, S_OUT);
}